// round 16
// baseline (speedup 1.0000x reference)
#include <cuda_runtime.h>
#include <cuda_bf16.h>
#include <math.h>
#include <stdint.h>

#define Bv 4
#define Tv 2048
#define Dv 256
#define Mv 128
#define Lv 16
#define Pv 2048   /* M*L */

// ---------------- scratch (device globals; no allocations allowed) ----------
__device__ float g_hr[Bv * Pv * Dv];       // head_rep  [B,P,D]
__device__ float g_tr[Bv * Pv * Dv];       // tail_rep  [B,P,D]
__device__ float g_pw[Bv * Pv];            // per-pair masked KL term
__device__ int   g_seli[Bv * Mv];          // per-mention argmax index
__device__ float g_selv[Bv * Mv];          // per-mention max score
__device__ __nv_bfloat16 g_xhi[Bv * Dv * Tv];  // X^T hi  [B][D][T]
__device__ __nv_bfloat16 g_xlo[Bv * Dv * Tv];  // X^T lo  [B][D][T]
__device__ __nv_bfloat16 g_w1h[Dv * 3 * Dv];   // w1^T hi [n=256][k=768]
__device__ __nv_bfloat16 g_w1l[Dv * 3 * Dv];   // w1^T lo [n=256][k=768]
__device__ __nv_bfloat16 g_rmh[Bv * Dv * Mv];  // repm^T hi [B][D][M]
__device__ __nv_bfloat16 g_rml[Bv * Dv * Mv];  // repm^T lo [B][D][M]

__device__ __forceinline__ uint32_t smem_u32(const void* p) {
    uint32_t a;
    asm("{ .reg .u64 t; cvta.to.shared.u64 t, %1; cvt.u32.u64 %0, t; }"
        : "=r"(a) : "l"(p));
    return a;
}
__device__ __forceinline__ void cp_async16(uint32_t dst, const void* src) {
    asm volatile("cp.async.cg.shared.global [%0], [%1], 16;"
                 :: "r"(dst), "l"(src));
}
#define CP_COMMIT() asm volatile("cp.async.commit_group;")
#define CP_WAIT0()  asm volatile("cp.async.wait_group 0;")

__device__ __forceinline__ uint32_t pk2(__nv_bfloat16 a, __nv_bfloat16 b) {
    return (uint32_t)__bfloat16_as_ushort(a) |
           ((uint32_t)__bfloat16_as_ushort(b) << 16);
}
__device__ __forceinline__ void mma_bf16(float* c, const uint32_t* a,
                                         const uint32_t* b) {
    asm volatile(
        "mma.sync.aligned.m16n8k16.row.col.f32.bf16.bf16.f32 "
        "{%0,%1,%2,%3}, {%4,%5,%6,%7}, {%8,%9}, {%0,%1,%2,%3};"
        : "+f"(c[0]), "+f"(c[1]), "+f"(c[2]), "+f"(c[3])
        : "r"(a[0]), "r"(a[1]), "r"(a[2]), "r"(a[3]), "r"(b[0]), "r"(b[1]));
}
#define LDM4(r0, r1, r2, r3, addr) \
    asm volatile("ldmatrix.sync.aligned.m8n8.x4.shared.b16 {%0,%1,%2,%3}, [%4];" \
                 : "=r"(r0), "=r"(r1), "=r"(r2), "=r"(r3) : "r"(addr))

// split a float4 into hi/lo bf16 pairs
__device__ __forceinline__ void split4(float4 v, uint2& hi, uint2& lo) {
    __nv_bfloat16 hx = __float2bfloat16(v.x), hy = __float2bfloat16(v.y);
    __nv_bfloat16 hz = __float2bfloat16(v.z), hw = __float2bfloat16(v.w);
    hi = make_uint2(pk2(hx, hy), pk2(hz, hw));
    lo = make_uint2(
        pk2(__float2bfloat16(v.x - __bfloat162float(hx)),
            __float2bfloat16(v.y - __bfloat162float(hy))),
        pk2(__float2bfloat16(v.z - __bfloat162float(hz)),
            __float2bfloat16(v.w - __bfloat162float(hw))));
}

// swizzled byte offset inside a 64B-row tile: seg (16B) XOR'd by row pair
__device__ __forceinline__ uint32_t swz64(int row, int seg) {
    return (uint32_t)(row * 64 + ((seg ^ ((row >> 1) & 3)) << 4));
}

// ---------------- prep (fused): X -> X^T hi/lo;  w1 -> w1^T hi/lo ------------
// grid (Tv/32, Dv/32, Bv+1); z<Bv: X-transpose for batch z; z==Bv: w1 (x<24).
__global__ void prep_all(const float* __restrict__ x,
                         const float* __restrict__ w1) {
    __shared__ float tile[32][33];
    const int tx = threadIdx.x, ty = threadIdx.y;
    if (blockIdx.z < Bv) {
        const int b = blockIdx.z, t0 = blockIdx.x * 32, d0 = blockIdx.y * 32;
#pragma unroll
        for (int i = 0; i < 4; i++)
            tile[ty + 8 * i][tx] =
                x[((size_t)b * Tv + t0 + ty + 8 * i) * Dv + d0 + tx];
        __syncthreads();
#pragma unroll
        for (int i = 0; i < 4; i++) {
            int d = d0 + ty + 8 * i, t = t0 + tx;
            float v = tile[tx][ty + 8 * i];
            __nv_bfloat16 h = __float2bfloat16(v);
            size_t off = ((size_t)b * Dv + d) * Tv + t;
            g_xhi[off] = h;
            g_xlo[off] = __float2bfloat16(v - __bfloat162float(h));
        }
    } else {
        if (blockIdx.x >= 3 * Dv / 32) return;   // w1 has 768 k-rows = 24 tiles
        const int k0 = blockIdx.x * 32, n0 = blockIdx.y * 32;
#pragma unroll
        for (int i = 0; i < 4; i++)
            tile[ty + 8 * i][tx] = w1[(size_t)(k0 + ty + 8 * i) * Dv + n0 + tx];
        __syncthreads();
#pragma unroll
        for (int i = 0; i < 4; i++) {
            int n = n0 + ty + 8 * i, k = k0 + tx;
            float v = tile[tx][ty + 8 * i];
            __nv_bfloat16 h = __float2bfloat16(v);
            g_w1h[(size_t)n * (3 * Dv) + k] = h;
            g_w1l[(size_t)n * (3 * Dv) + k] =
                __float2bfloat16(v - __bfloat162float(h));
        }
    }
}

// ---------------- kernel 1: bf16x3 GEMM, 64x256 tile, 2 CTAs/SM (R9 best) ----
#define R_AH 0
#define R_AL 4096
#define R_BH 8192
#define R_BL 24576
#define R_STAGE 40960
#define R_SMEM (2 * R_STAGE)
#define NCHUNK 64

__global__ __launch_bounds__(128, 2)
void gemm_rep_mma(const float* __restrict__ head, const float* __restrict__ tail) {
    extern __shared__ char smem[];
    const uint32_t sbase = smem_u32(smem);
    const int tid = threadIdx.x, wid = tid >> 5, lane = tid & 31;
    const int z = blockIdx.y, b = z >> 1;
    const float* A = ((z & 1) ? tail : head) + (size_t)b * Pv * Tv
                   + (size_t)blockIdx.x * 64 * Tv;
    float* C = ((z & 1) ? g_tr : g_hr) + (size_t)b * Pv * Dv
             + (size_t)blockIdx.x * 64 * Dv;
    const __nv_bfloat16* XH = g_xhi + (size_t)b * Dv * Tv;
    const __nv_bfloat16* XL = g_xlo + (size_t)b * Dv * Tv;

    const int n0w = wid * 64;
    const int mat = lane >> 3, r8 = lane & 7;
    const int a_rrel = (mat & 1) * 8 + r8;
    const int a_msk  = (a_rrel >> 1) & 3;
    const int a_matk = mat >> 1;
    const int b_rrel = (mat >> 1) * 8 + r8;
    const int b_msk  = (b_rrel >> 1) & 3;
    const int b_matk = mat & 1;
    const int ac4 = tid & 7;

    float acc[4][8][4];
#pragma unroll
    for (int i = 0; i < 4; i++)
#pragma unroll
        for (int j = 0; j < 8; j++)
#pragma unroll
            for (int q = 0; q < 4; q++) acc[i][j][q] = 0.f;

    {
#pragma unroll
        for (int l = 0; l < 8; l++) {
            int q = tid + l * 128, d = q >> 2, seg = q & 3;
            uint32_t so = swz64(d, seg);
            cp_async16(sbase + R_BH + so, XH + (size_t)d * Tv + seg * 8);
            cp_async16(sbase + R_BL + so, XL + (size_t)d * Tv + seg * 8);
        }
        CP_COMMIT();
#pragma unroll
        for (int l = 0; l < 4; l++) {
            int q = tid + l * 128, row = q >> 3;
            float4 v = *(const float4*)&A[(size_t)row * Tv + ac4 * 4];
            uint2 hi, lo;
            split4(v, hi, lo);
            uint32_t so = swz64(row, ac4 >> 1) + (ac4 & 1) * 8;
            *(uint2*)(smem + R_AH + so) = hi;
            *(uint2*)(smem + R_AL + so) = lo;
        }
        CP_WAIT0();
        __syncthreads();
    }

    for (int c = 0; c < NCHUNK; c++) {
        const int s = c & 1;
        const uint32_t bb = sbase + s * R_STAGE;
        const bool more = (c + 1 < NCHUNK);
        float4 pa[4];
        if (more) {
            const int k1 = (c + 1) * 32;
            const uint32_t nbuf = sbase + (s ^ 1) * R_STAGE;
#pragma unroll
            for (int l = 0; l < 8; l++) {
                int q = tid + l * 128, d = q >> 2, seg = q & 3;
                uint32_t so = swz64(d, seg);
                cp_async16(nbuf + R_BH + so, XH + (size_t)d * Tv + k1 + seg * 8);
                cp_async16(nbuf + R_BL + so, XL + (size_t)d * Tv + k1 + seg * 8);
            }
            CP_COMMIT();
#pragma unroll
            for (int l = 0; l < 4; l++) {
                int q = tid + l * 128, row = q >> 3;
                pa[l] = *(const float4*)&A[(size_t)row * Tv + k1 + ac4 * 4];
            }
        }
#pragma unroll
        for (int ks = 0; ks < 2; ks++) {
            uint32_t ah[4][4];
#pragma unroll
            for (int i = 0; i < 4; i++) {
                int row = 16 * i + a_rrel;
                uint32_t ao = (uint32_t)(row * 64 +
                    (((ks * 2 + a_matk) ^ a_msk) << 4));
                LDM4(ah[i][0], ah[i][1], ah[i][2], ah[i][3], bb + R_AH + ao);
            }
            uint32_t bh[8][2];
#pragma unroll
            for (int jj = 0; jj < 4; jj++) {
                int row = n0w + 16 * jj + b_rrel;
                uint32_t bo = (uint32_t)(row * 64 +
                    (((ks * 2 + b_matk) ^ b_msk) << 4));
                LDM4(bh[2 * jj][0], bh[2 * jj][1], bh[2 * jj + 1][0],
                     bh[2 * jj + 1][1], bb + R_BH + bo);
            }
#pragma unroll
            for (int i = 0; i < 4; i++)
#pragma unroll
                for (int j = 0; j < 8; j++)
                    mma_bf16(acc[i][j], ah[i], bh[j]);
            uint32_t bl[8][2];
#pragma unroll
            for (int jj = 0; jj < 4; jj++) {
                int row = n0w + 16 * jj + b_rrel;
                uint32_t bo = (uint32_t)(row * 64 +
                    (((ks * 2 + b_matk) ^ b_msk) << 4));
                LDM4(bl[2 * jj][0], bl[2 * jj][1], bl[2 * jj + 1][0],
                     bl[2 * jj + 1][1], bb + R_BL + bo);
            }
#pragma unroll
            for (int i = 0; i < 4; i++)
#pragma unroll
                for (int j = 0; j < 8; j++)
                    mma_bf16(acc[i][j], ah[i], bl[j]);
            uint32_t al[4][4];
#pragma unroll
            for (int i = 0; i < 4; i++) {
                int row = 16 * i + a_rrel;
                uint32_t ao = (uint32_t)(row * 64 +
                    (((ks * 2 + a_matk) ^ a_msk) << 4));
                LDM4(al[i][0], al[i][1], al[i][2], al[i][3], bb + R_AL + ao);
            }
#pragma unroll
            for (int i = 0; i < 4; i++)
#pragma unroll
                for (int j = 0; j < 8; j++)
                    mma_bf16(acc[i][j], al[i], bh[j]);
        }
        if (more) {
            char* nb = smem + (s ^ 1) * R_STAGE;
#pragma unroll
            for (int l = 0; l < 4; l++) {
                int q = tid + l * 128, row = q >> 3;
                uint2 hi, lo;
                split4(pa[l], hi, lo);
                uint32_t so = swz64(row, ac4 >> 1) + (ac4 & 1) * 8;
                *(uint2*)(nb + R_AH + so) = hi;
                *(uint2*)(nb + R_AL + so) = lo;
            }
        }
        CP_WAIT0();
        __syncthreads();
    }

    const int g = lane >> 2, t2 = (lane & 3) * 2;
#pragma unroll
    for (int i = 0; i < 4; i++)
#pragma unroll
        for (int j = 0; j < 8; j++) {
            int rr = 16 * i + g, cc = n0w + 8 * j + t2;
            *(float2*)&C[(size_t)rr * Dv + cc] =
                make_float2(acc[i][j][0], acc[i][j][1]);
            *(float2*)&C[(size_t)(rr + 8) * Dv + cc] =
                make_float2(acc[i][j][2], acc[i][j][3]);
        }
}

// ---------------- kernel 2: MLP + fused logits/KL/argmax, 32x256 tile --------
#define M_AH 0
#define M_AL 2048
#define M_BH 4096
#define M_BL 20480
#define M_STAGE 36864
#define M_SMEM (2 * M_STAGE)
#define M_NCHUNK 24

__global__ __launch_bounds__(128, 2)
void gemm_mlp_mma(const float* __restrict__ b1, const float* __restrict__ w2,
                  const float* __restrict__ b2, const float* __restrict__ label,
                  const int* __restrict__ mask) {
    extern __shared__ char smem[];
    const uint32_t sbase = smem_u32(smem);
    const int tid = threadIdx.x, wid = tid >> 5, lane = tid & 31;
    const int row0 = blockIdx.x * 32;

    const int n0w = wid * 64;
    const int mat = lane >> 3, r8 = lane & 7;
    const int a_rrel = (mat & 1) * 8 + r8;
    const int a_msk  = (a_rrel >> 1) & 3;
    const int a_matk = mat >> 1;
    const int b_rrel = (mat >> 1) * 8 + r8;
    const int b_msk  = (b_rrel >> 1) & 3;
    const int b_matk = mat & 1;
    const int ac4 = tid & 7;

    float acc[2][8][4];
#pragma unroll
    for (int i = 0; i < 2; i++)
#pragma unroll
        for (int j = 0; j < 8; j++)
#pragma unroll
            for (int q = 0; q < 4; q++) acc[i][j][q] = 0.f;

    {
#pragma unroll
        for (int l = 0; l < 8; l++) {
            int q = tid + l * 128, d = q >> 2, seg = q & 3;
            uint32_t so = swz64(d, seg);
            cp_async16(sbase + M_BH + so, g_w1h + (size_t)d * (3 * Dv) + seg * 8);
            cp_async16(sbase + M_BL + so, g_w1l + (size_t)d * (3 * Dv) + seg * 8);
        }
        CP_COMMIT();
#pragma unroll
        for (int l = 0; l < 2; l++) {
            int q = tid + l * 128, row = q >> 3;
            float4 v = *(const float4*)&g_hr[(size_t)(row0 + row) * Dv + ac4 * 4];
            uint2 hi, lo;
            split4(v, hi, lo);
            uint32_t so = swz64(row, ac4 >> 1) + (ac4 & 1) * 8;
            *(uint2*)(smem + M_AH + so) = hi;
            *(uint2*)(smem + M_AL + so) = lo;
        }
        CP_WAIT0();
        __syncthreads();
    }

    for (int c = 0; c < M_NCHUNK; c++) {
        const int s = c & 1;
        const uint32_t bb = sbase + s * M_STAGE;
        const bool more = (c + 1 < M_NCHUNK);
        float4 pa[2], pt[2];
        int nregion = 0;
        if (more) {
            const int c1 = c + 1;
            nregion = c1 >> 3;
            const int kk = (c1 & 7) * 32;
            const int k1 = c1 * 32;
            const uint32_t nbuf = sbase + (s ^ 1) * M_STAGE;
#pragma unroll
            for (int l = 0; l < 8; l++) {
                int q = tid + l * 128, d = q >> 2, seg = q & 3;
                uint32_t so = swz64(d, seg);
                cp_async16(nbuf + M_BH + so,
                           g_w1h + (size_t)d * (3 * Dv) + k1 + seg * 8);
                cp_async16(nbuf + M_BL + so,
                           g_w1l + (size_t)d * (3 * Dv) + k1 + seg * 8);
            }
            CP_COMMIT();
#pragma unroll
            for (int l = 0; l < 2; l++) {
                int q = tid + l * 128, row = q >> 3;
                size_t off = (size_t)(row0 + row) * Dv + kk + ac4 * 4;
                if (nregion == 0) pa[l] = *(const float4*)&g_hr[off];
                else if (nregion == 1) pa[l] = *(const float4*)&g_tr[off];
                else {
                    pa[l] = *(const float4*)&g_hr[off];
                    pt[l] = *(const float4*)&g_tr[off];
                }
            }
        }
#pragma unroll
        for (int ks = 0; ks < 2; ks++) {
            uint32_t ah[2][4];
#pragma unroll
            for (int i = 0; i < 2; i++) {
                int row = 16 * i + a_rrel;
                uint32_t ao = (uint32_t)(row * 64 +
                    (((ks * 2 + a_matk) ^ a_msk) << 4));
                LDM4(ah[i][0], ah[i][1], ah[i][2], ah[i][3], bb + M_AH + ao);
            }
            uint32_t bh[8][2];
#pragma unroll
            for (int jj = 0; jj < 4; jj++) {
                int row = n0w + 16 * jj + b_rrel;
                uint32_t bo = (uint32_t)(row * 64 +
                    (((ks * 2 + b_matk) ^ b_msk) << 4));
                LDM4(bh[2 * jj][0], bh[2 * jj][1], bh[2 * jj + 1][0],
                     bh[2 * jj + 1][1], bb + M_BH + bo);
            }
#pragma unroll
            for (int i = 0; i < 2; i++)
#pragma unroll
                for (int j = 0; j < 8; j++)
                    mma_bf16(acc[i][j], ah[i], bh[j]);
            uint32_t bl[8][2];
#pragma unroll
            for (int jj = 0; jj < 4; jj++) {
                int row = n0w + 16 * jj + b_rrel;
                uint32_t bo = (uint32_t)(row * 64 +
                    (((ks * 2 + b_matk) ^ b_msk) << 4));
                LDM4(bl[2 * jj][0], bl[2 * jj][1], bl[2 * jj + 1][0],
                     bl[2 * jj + 1][1], bb + M_BL + bo);
            }
#pragma unroll
            for (int i = 0; i < 2; i++)
#pragma unroll
                for (int j = 0; j < 8; j++)
                    mma_bf16(acc[i][j], ah[i], bl[j]);
            uint32_t al[2][4];
#pragma unroll
            for (int i = 0; i < 2; i++) {
                int row = 16 * i + a_rrel;
                uint32_t ao = (uint32_t)(row * 64 +
                    (((ks * 2 + a_matk) ^ a_msk) << 4));
                LDM4(al[i][0], al[i][1], al[i][2], al[i][3], bb + M_AL + ao);
            }
#pragma unroll
            for (int i = 0; i < 2; i++)
#pragma unroll
                for (int j = 0; j < 8; j++)
                    mma_bf16(acc[i][j], al[i], bh[j]);
        }
        if (more) {
            char* nb = smem + (s ^ 1) * M_STAGE;
#pragma unroll
            for (int l = 0; l < 2; l++) {
                int q = tid + l * 128, row = q >> 3;
                float4 v = pa[l];
                if (nregion == 2) {
                    v.x *= pt[l].x; v.y *= pt[l].y; v.z *= pt[l].z; v.w *= pt[l].w;
                }
                uint2 hi, lo;
                split4(v, hi, lo);
                uint32_t so = swz64(row, ac4 >> 1) + (ac4 & 1) * 8;
                *(uint2*)(nb + M_AH + so) = hi;
                *(uint2*)(nb + M_AL + so) = lo;
            }
        }
        CP_WAIT0();
        __syncthreads();
    }

    // ---- fused epilogue: relu(acc+b1) @ w2 partials, reduce, KL, argmax -----
    const int g = lane >> 2, t2 = (lane & 3) * 2;
    float s0[4] = {0.f, 0.f, 0.f, 0.f}, s1[4] = {0.f, 0.f, 0.f, 0.f};
#pragma unroll
    for (int j = 0; j < 8; j++)
#pragma unroll
        for (int e = 0; e < 2; e++) {
            int col = n0w + 8 * j + t2 + e;
            float bb1 = b1[col];
            float w20 = w2[col * 2], w21 = w2[col * 2 + 1];
#pragma unroll
            for (int i = 0; i < 2; i++) {
                float h0 = fmaxf(acc[i][j][e] + bb1, 0.f);       // row 16i+g
                float h1 = fmaxf(acc[i][j][e + 2] + bb1, 0.f);   // row 16i+8+g
                s0[i * 2 + 0] = fmaf(h0, w20, s0[i * 2 + 0]);
                s1[i * 2 + 0] = fmaf(h0, w21, s1[i * 2 + 0]);
                s0[i * 2 + 1] = fmaf(h1, w20, s0[i * 2 + 1]);
                s1[i * 2 + 1] = fmaf(h1, w21, s1[i * 2 + 1]);
            }
        }
#pragma unroll
    for (int sl = 0; sl < 4; sl++) {
        s0[sl] += __shfl_xor_sync(0xffffffffu, s0[sl], 1);
        s0[sl] += __shfl_xor_sync(0xffffffffu, s0[sl], 2);
        s1[sl] += __shfl_xor_sync(0xffffffffu, s1[sl], 1);
        s1[sl] += __shfl_xor_sync(0xffffffffu, s1[sl], 2);
    }
    float* sred = (float*)smem;   // [4 warps][32 rows][2]
    if ((lane & 3) == 0) {
#pragma unroll
        for (int sl = 0; sl < 4; sl++) {
            int row = (sl >> 1) * 16 + (sl & 1) * 8 + g;
            sred[(wid * 32 + row) * 2 + 0] = s0[sl];
            sred[(wid * 32 + row) * 2 + 1] = s1[sl];
        }
    }
    __syncthreads();
    if (tid < 32) {
        int r = tid;
        float l0 = b2[0], l1 = b2[1];
#pragma unroll
        for (int w = 0; w < 4; w++) {
            l0 += sred[(w * 32 + r) * 2 + 0];
            l1 += sred[(w * 32 + r) * 2 + 1];
        }
        int gw = row0 + r;
        float mx = fmaxf(l0, l1);
        float lse = mx + logf(expf(l0 - mx) + expf(l1 - mx));
        float a0 = label[gw * 2 + 0];
        float a1 = label[gw * 2 + 1];
        float pw = (a0 > 0.f ? a0 * logf(fmaxf(a0, 1e-38f)) : 0.f) - a0 * (l0 - lse)
                 + (a1 > 0.f ? a1 * logf(fmaxf(a1, 1e-38f)) : 0.f) - a1 * (l1 - lse);
        g_pw[gw] = mask[gw] ? pw : 0.f;
        // fused per-mention argmax over the 16-lane group (first-max semantics)
        float v = l1;
        int idx = r & 15;
#pragma unroll
        for (int o = 8; o; o >>= 1) {
            float ov = __shfl_down_sync(0xffffffffu, v, o, 16);
            int oi = __shfl_down_sync(0xffffffffu, idx, o, 16);
            if (ov > v || (ov == v && oi < idx)) { v = ov; idx = oi; }
        }
        if ((r & 15) == 0) {
            int mention = gw >> 4;     // global index into [Bv*Mv)
            g_seli[mention] = idx;
            g_selv[mention] = v;
        }
    }
}

// ---------------- kernel 3: select (precomputed argmax) + transpose ----------
__global__ void select_transpose() {
    __shared__ float tile[32][33];
    __shared__ int sidx[32];
    __shared__ float sval[32];
    const int b = blockIdx.z, m0 = blockIdx.x * 32, d0 = blockIdx.y * 32;
    const int tx = threadIdx.x, ty = threadIdx.y;

    if (ty == 0) {
        sidx[tx] = g_seli[b * Mv + m0 + tx];
        sval[tx] = g_selv[b * Mv + m0 + tx];
    }
    __syncthreads();
#pragma unroll
    for (int i = 0; i < 4; i++) {
        int m = ty + 8 * i;
        size_t row = (size_t)b * Pv + (size_t)(m0 + m) * Lv + sidx[m];
        tile[m][tx] = g_tr[row * Dv + d0 + tx] * sval[m];
    }
    __syncthreads();
#pragma unroll
    for (int i = 0; i < 4; i++) {
        int d = d0 + ty + 8 * i, m = m0 + tx;
        float v = tile[tx][ty + 8 * i];
        __nv_bfloat16 h = __float2bfloat16(v);
        size_t off = ((size_t)b * Dv + d) * Mv + m;
        g_rmh[off] = h;
        g_rml[off] = __float2bfloat16(v - __bfloat162float(h));
    }
}

// ---------------- kernel 4: merge via bf16x3 mma: out = x + cmp^T @ repm -----
#define G_NCHUNK 4

__global__ __launch_bounds__(128, 2)
void merge_mma(const float* __restrict__ x, const float* __restrict__ cmp,
               float* __restrict__ out) {
    extern __shared__ char smem[];
    const uint32_t sbase = smem_u32(smem);
    const int tid = threadIdx.x, wid = tid >> 5, lane = tid & 31;
    const int b = blockIdx.y, t0 = blockIdx.x * 64;
    const float* CM = cmp + (size_t)b * Mv * Tv;
    const __nv_bfloat16* RH = g_rmh + (size_t)b * Dv * Mv;
    const __nv_bfloat16* RL = g_rml + (size_t)b * Dv * Mv;

    const int n0w = wid * 64;
    const int mat = lane >> 3, r8 = lane & 7;
    const int a_rrel = (mat & 1) * 8 + r8;
    const int a_msk  = (a_rrel >> 1) & 3;
    const int a_matk = mat >> 1;
    const int b_rrel = (mat >> 1) * 8 + r8;
    const int b_msk  = (b_rrel >> 1) & 3;
    const int b_matk = mat & 1;

    const int am = tid >> 2, atoff = (tid & 3) * 16;

    float acc[4][8][4];
#pragma unroll
    for (int i = 0; i < 4; i++)
#pragma unroll
        for (int j = 0; j < 8; j++)
#pragma unroll
            for (int q = 0; q < 4; q++) acc[i][j][q] = 0.f;

    {
#pragma unroll
        for (int l = 0; l < 8; l++) {
            int q = tid + l * 128, d = q >> 2, seg = q & 3;
            uint32_t so = swz64(d, seg);
            cp_async16(sbase + R_BH + so, RH + (size_t)d * Mv + seg * 8);
            cp_async16(sbase + R_BL + so, RL + (size_t)d * Mv + seg * 8);
        }
        CP_COMMIT();
#pragma unroll
        for (int l = 0; l < 4; l++) {
            float4 v = *(const float4*)&CM[(size_t)am * Tv + t0 + atoff + l * 4];
            float f[4] = {v.x, v.y, v.z, v.w};
#pragma unroll
            for (int fi = 0; fi < 4; fi++) {
                int t = atoff + l * 4 + fi;
                __nv_bfloat16 h = __float2bfloat16(f[fi]);
                uint32_t so = (uint32_t)(t * 64 +
                    ((((am >> 3) ^ ((t >> 1) & 3)) << 4)) + (am & 7) * 2);
                *(__nv_bfloat16*)(smem + R_AH + so) = h;
                *(__nv_bfloat16*)(smem + R_AL + so) =
                    __float2bfloat16(f[fi] - __bfloat162float(h));
            }
        }
        CP_WAIT0();
        __syncthreads();
    }

    for (int c = 0; c < G_NCHUNK; c++) {
        const int s = c & 1;
        const uint32_t bb = sbase + s * R_STAGE;
        const bool more = (c + 1 < G_NCHUNK);
        float4 pa[4];
        if (more) {
            const int m1 = (c + 1) * 32;
            const uint32_t nbuf = sbase + (s ^ 1) * R_STAGE;
#pragma unroll
            for (int l = 0; l < 8; l++) {
                int q = tid + l * 128, d = q >> 2, seg = q & 3;
                uint32_t so = swz64(d, seg);
                cp_async16(nbuf + R_BH + so, RH + (size_t)d * Mv + m1 + seg * 8);
                cp_async16(nbuf + R_BL + so, RL + (size_t)d * Mv + m1 + seg * 8);
            }
            CP_COMMIT();
#pragma unroll
            for (int l = 0; l < 4; l++)
                pa[l] = *(const float4*)&CM[(size_t)(m1 + am) * Tv + t0 + atoff + l * 4];
        }
#pragma unroll
        for (int ks = 0; ks < 2; ks++) {
            uint32_t ah[4][4];
#pragma unroll
            for (int i = 0; i < 4; i++) {
                int row = 16 * i + a_rrel;
                uint32_t ao = (uint32_t)(row * 64 +
                    (((ks * 2 + a_matk) ^ a_msk) << 4));
                LDM4(ah[i][0], ah[i][1], ah[i][2], ah[i][3], bb + R_AH + ao);
            }
            uint32_t bh[8][2];
#pragma unroll
            for (int jj = 0; jj < 4; jj++) {
                int row = n0w + 16 * jj + b_rrel;
                uint32_t bo = (uint32_t)(row * 64 +
                    (((ks * 2 + b_matk) ^ b_msk) << 4));
                LDM4(bh[2 * jj][0], bh[2 * jj][1], bh[2 * jj + 1][0],
                     bh[2 * jj + 1][1], bb + R_BH + bo);
            }
#pragma unroll
            for (int i = 0; i < 4; i++)
#pragma unroll
                for (int j = 0; j < 8; j++)
                    mma_bf16(acc[i][j], ah[i], bh[j]);
            uint32_t bl[8][2];
#pragma unroll
            for (int jj = 0; jj < 4; jj++) {
                int row = n0w + 16 * jj + b_rrel;
                uint32_t bo = (uint32_t)(row * 64 +
                    (((ks * 2 + b_matk) ^ b_msk) << 4));
                LDM4(bl[2 * jj][0], bl[2 * jj][1], bl[2 * jj + 1][0],
                     bl[2 * jj + 1][1], bb + R_BL + bo);
            }
#pragma unroll
            for (int i = 0; i < 4; i++)
#pragma unroll
                for (int j = 0; j < 8; j++)
                    mma_bf16(acc[i][j], ah[i], bl[j]);
            uint32_t al[4][4];
#pragma unroll
            for (int i = 0; i < 4; i++) {
                int row = 16 * i + a_rrel;
                uint32_t ao = (uint32_t)(row * 64 +
                    (((ks * 2 + a_matk) ^ a_msk) << 4));
                LDM4(al[i][0], al[i][1], al[i][2], al[i][3], bb + R_AL + ao);
            }
#pragma unroll
            for (int i = 0; i < 4; i++)
#pragma unroll
                for (int j = 0; j < 8; j++)
                    mma_bf16(acc[i][j], al[i], bh[j]);
        }
        if (more) {
            char* nb = smem + (s ^ 1) * R_STAGE;
#pragma unroll
            for (int l = 0; l < 4; l++) {
                float f[4] = {pa[l].x, pa[l].y, pa[l].z, pa[l].w};
#pragma unroll
                for (int fi = 0; fi < 4; fi++) {
                    int t = atoff + l * 4 + fi;
                    __nv_bfloat16 h = __float2bfloat16(f[fi]);
                    uint32_t so = (uint32_t)(t * 64 +
                        ((((am >> 3) ^ ((t >> 1) & 3)) << 4)) + (am & 7) * 2);
                    *(__nv_bfloat16*)(nb + R_AH + so) = h;
                    *(__nv_bfloat16*)(nb + R_AL + so) =
                        __float2bfloat16(f[fi] - __bfloat162float(h));
                }
            }
        }
        CP_WAIT0();
        __syncthreads();
    }

    const int g = lane >> 2, t2 = (lane & 3) * 2;
#pragma unroll
    for (int i = 0; i < 4; i++)
#pragma unroll
        for (int j = 0; j < 8; j++) {
            int rr = t0 + 16 * i + g, cc = n0w + 8 * j + t2;
            size_t base = ((size_t)b * Tv + rr) * Dv + cc;
            float2 x0 = *(const float2*)&x[base];
            float2 x1 = *(const float2*)&x[base + (size_t)8 * Dv];
            *(float2*)&out[base] =
                make_float2(x0.x + acc[i][j][0], x0.y + acc[i][j][1]);
            *(float2*)&out[base + (size_t)8 * Dv] =
                make_float2(x1.x + acc[i][j][2], x1.y + acc[i][j][3]);
        }
}

// ---------------- kernel 5: deterministic loss reduction ---------------------
__global__ void loss_kernel(const int* __restrict__ mask,
                            float* __restrict__ out_loss) {
    __shared__ float sh[1024];
    __shared__ int shc[1024];
    const int tid = threadIdx.x;
    float s = 0.f;
    int c = 0;
    for (int i = tid; i < Bv * Pv; i += 1024) {
        s += g_pw[i];
        c += mask[i] ? 1 : 0;
    }
    sh[tid] = s;
    shc[tid] = c;
    __syncthreads();
    for (int o = 512; o; o >>= 1) {
        if (tid < o) { sh[tid] += sh[tid + o]; shc[tid] += shc[tid + o]; }
        __syncthreads();
    }
    if (tid == 0) *out_loss = sh[0] / ((float)shc[0] * 2.0f);
}

// ---------------- launch -----------------------------------------------------
extern "C" void kernel_launch(void* const* d_in, const int* in_sizes, int n_in,
                              void* d_out, int out_size) {
    const float* head = (const float*)d_in[0];
    const float* tail = (const float*)d_in[1];
    /* d_in[2] = lens (unused: uniform L) */
    const float* x    = (const float*)d_in[3];
    const float* cmp  = (const float*)d_in[4];
    const float* lab  = (const float*)d_in[5];
    const int*   mask = (const int*)d_in[6];
    const float* w1 = (const float*)d_in[7];
    const float* b1 = (const float*)d_in[8];
    const float* w2 = (const float*)d_in[9];
    const float* b2 = (const float*)d_in[10];
    float* out = (float*)d_out;

    cudaFuncSetAttribute(gemm_rep_mma,
                         cudaFuncAttributeMaxDynamicSharedMemorySize, R_SMEM);
    cudaFuncSetAttribute(gemm_mlp_mma,
                         cudaFuncAttributeMaxDynamicSharedMemorySize, M_SMEM);
    cudaFuncSetAttribute(merge_mma,
                         cudaFuncAttributeMaxDynamicSharedMemorySize, R_SMEM);

    prep_all<<<dim3(Tv / 32, Dv / 32, Bv + 1), dim3(32, 8)>>>(x, w1); // #1
    gemm_rep_mma<<<dim3(Pv / 64, Bv * 2), 128, R_SMEM>>>(head, tail); // #2
    gemm_mlp_mma<<<(Bv * Pv) / 32, 128, M_SMEM>>>(b1, w2, b2, lab, mask); // #3
    select_transpose<<<dim3(Mv / 32, Dv / 32, Bv), dim3(32, 8)>>>();
    merge_mma<<<dim3(Tv / 64, Bv), 128, R_SMEM>>>(x, cmp, out);
    loss_kernel<<<1, 1024>>>(mask, out + (out_size - 1));
}

// round 17
// speedup vs baseline: 1.0303x; 1.0303x over previous
#include <cuda_runtime.h>
#include <cuda_bf16.h>
#include <math.h>
#include <stdint.h>

#define Bv 4
#define Tv 2048
#define Dv 256
#define Mv 128
#define Lv 16
#define Pv 2048   /* M*L */

// ---------------- scratch (device globals; no allocations allowed) ----------
__device__ float g_hr[Bv * Pv * Dv];       // head_rep  [B,P,D]
__device__ float g_tr[Bv * Pv * Dv];       // tail_rep  [B,P,D]
__device__ float g_pw[Bv * Pv];            // per-pair masked KL term
__device__ int   g_seli[Bv * Mv];          // per-mention argmax index
__device__ float g_selv[Bv * Mv];          // per-mention max score
__device__ __nv_bfloat16 g_xhi[Bv * Dv * Tv];  // X^T hi  [B][D][T]
__device__ __nv_bfloat16 g_xlo[Bv * Dv * Tv];  // X^T lo  [B][D][T]
__device__ __nv_bfloat16 g_w1h[Dv * 3 * Dv];   // w1^T hi [n=256][k=768]
__device__ __nv_bfloat16 g_w1l[Dv * 3 * Dv];   // w1^T lo [n=256][k=768]
__device__ __nv_bfloat16 g_rmh[Bv * Dv * Mv];  // repm^T hi [B][D][M]
__device__ __nv_bfloat16 g_rml[Bv * Dv * Mv];  // repm^T lo [B][D][M]

__device__ __forceinline__ uint32_t smem_u32(const void* p) {
    uint32_t a;
    asm("{ .reg .u64 t; cvta.to.shared.u64 t, %1; cvt.u32.u64 %0, t; }"
        : "=r"(a) : "l"(p));
    return a;
}
__device__ __forceinline__ void cp_async16(uint32_t dst, const void* src) {
    asm volatile("cp.async.cg.shared.global [%0], [%1], 16;"
                 :: "r"(dst), "l"(src));
}
#define CP_COMMIT() asm volatile("cp.async.commit_group;")
#define CP_WAIT0()  asm volatile("cp.async.wait_group 0;")

__device__ __forceinline__ uint32_t pk2(__nv_bfloat16 a, __nv_bfloat16 b) {
    return (uint32_t)__bfloat16_as_ushort(a) |
           ((uint32_t)__bfloat16_as_ushort(b) << 16);
}
__device__ __forceinline__ void mma_bf16(float* c, const uint32_t* a,
                                         const uint32_t* b) {
    asm volatile(
        "mma.sync.aligned.m16n8k16.row.col.f32.bf16.bf16.f32 "
        "{%0,%1,%2,%3}, {%4,%5,%6,%7}, {%8,%9}, {%0,%1,%2,%3};"
        : "+f"(c[0]), "+f"(c[1]), "+f"(c[2]), "+f"(c[3])
        : "r"(a[0]), "r"(a[1]), "r"(a[2]), "r"(a[3]), "r"(b[0]), "r"(b[1]));
}
#define LDM4(r0, r1, r2, r3, addr) \
    asm volatile("ldmatrix.sync.aligned.m8n8.x4.shared.b16 {%0,%1,%2,%3}, [%4];" \
                 : "=r"(r0), "=r"(r1), "=r"(r2), "=r"(r3) : "r"(addr))

// split a float4 into hi/lo bf16 pairs
__device__ __forceinline__ void split4(float4 v, uint2& hi, uint2& lo) {
    __nv_bfloat16 hx = __float2bfloat16(v.x), hy = __float2bfloat16(v.y);
    __nv_bfloat16 hz = __float2bfloat16(v.z), hw = __float2bfloat16(v.w);
    hi = make_uint2(pk2(hx, hy), pk2(hz, hw));
    lo = make_uint2(
        pk2(__float2bfloat16(v.x - __bfloat162float(hx)),
            __float2bfloat16(v.y - __bfloat162float(hy))),
        pk2(__float2bfloat16(v.z - __bfloat162float(hz)),
            __float2bfloat16(v.w - __bfloat162float(hw))));
}

// swizzled byte offset inside a 64B-row tile: seg (16B) XOR'd by row pair
__device__ __forceinline__ uint32_t swz64(int row, int seg) {
    return (uint32_t)(row * 64 + ((seg ^ ((row >> 1) & 3)) << 4));
}

// ---------------- prep (fused): X -> X^T hi/lo;  w1 -> w1^T hi/lo ------------
// grid (Tv/32, Dv/32, Bv+1); z<Bv: X-transpose for batch z; z==Bv: w1 (x<24).
__global__ void prep_all(const float* __restrict__ x,
                         const float* __restrict__ w1) {
    __shared__ float tile[32][33];
    const int tx = threadIdx.x, ty = threadIdx.y;
    if (blockIdx.z < Bv) {
        const int b = blockIdx.z, t0 = blockIdx.x * 32, d0 = blockIdx.y * 32;
#pragma unroll
        for (int i = 0; i < 4; i++)
            tile[ty + 8 * i][tx] =
                x[((size_t)b * Tv + t0 + ty + 8 * i) * Dv + d0 + tx];
        __syncthreads();
#pragma unroll
        for (int i = 0; i < 4; i++) {
            int d = d0 + ty + 8 * i, t = t0 + tx;
            float v = tile[tx][ty + 8 * i];
            __nv_bfloat16 h = __float2bfloat16(v);
            size_t off = ((size_t)b * Dv + d) * Tv + t;
            g_xhi[off] = h;
            g_xlo[off] = __float2bfloat16(v - __bfloat162float(h));
        }
    } else {
        if (blockIdx.x >= 3 * Dv / 32) return;   // w1 has 768 k-rows = 24 tiles
        const int k0 = blockIdx.x * 32, n0 = blockIdx.y * 32;
#pragma unroll
        for (int i = 0; i < 4; i++)
            tile[ty + 8 * i][tx] = w1[(size_t)(k0 + ty + 8 * i) * Dv + n0 + tx];
        __syncthreads();
#pragma unroll
        for (int i = 0; i < 4; i++) {
            int n = n0 + ty + 8 * i, k = k0 + tx;
            float v = tile[tx][ty + 8 * i];
            __nv_bfloat16 h = __float2bfloat16(v);
            g_w1h[(size_t)n * (3 * Dv) + k] = h;
            g_w1l[(size_t)n * (3 * Dv) + k] =
                __float2bfloat16(v - __bfloat162float(h));
        }
    }
}

// ---------------- kernel 1: bf16x3 GEMM, 64x256 tile, 2 CTAs/SM (R9 best) ----
#define R_AH 0
#define R_AL 4096
#define R_BH 8192
#define R_BL 24576
#define R_STAGE 40960
#define R_SMEM (2 * R_STAGE)
#define NCHUNK 64

__global__ __launch_bounds__(128, 2)
void gemm_rep_mma(const float* __restrict__ head, const float* __restrict__ tail) {
    extern __shared__ char smem[];
    const uint32_t sbase = smem_u32(smem);
    const int tid = threadIdx.x, wid = tid >> 5, lane = tid & 31;
    const int z = blockIdx.y, b = z >> 1;
    const float* A = ((z & 1) ? tail : head) + (size_t)b * Pv * Tv
                   + (size_t)blockIdx.x * 64 * Tv;
    float* C = ((z & 1) ? g_tr : g_hr) + (size_t)b * Pv * Dv
             + (size_t)blockIdx.x * 64 * Dv;
    const __nv_bfloat16* XH = g_xhi + (size_t)b * Dv * Tv;
    const __nv_bfloat16* XL = g_xlo + (size_t)b * Dv * Tv;

    const int n0w = wid * 64;
    const int mat = lane >> 3, r8 = lane & 7;
    const int a_rrel = (mat & 1) * 8 + r8;
    const int a_msk  = (a_rrel >> 1) & 3;
    const int a_matk = mat >> 1;
    const int b_rrel = (mat >> 1) * 8 + r8;
    const int b_msk  = (b_rrel >> 1) & 3;
    const int b_matk = mat & 1;
    const int ac4 = tid & 7;

    float acc[4][8][4];
#pragma unroll
    for (int i = 0; i < 4; i++)
#pragma unroll
        for (int j = 0; j < 8; j++)
#pragma unroll
            for (int q = 0; q < 4; q++) acc[i][j][q] = 0.f;

    {
#pragma unroll
        for (int l = 0; l < 8; l++) {
            int q = tid + l * 128, d = q >> 2, seg = q & 3;
            uint32_t so = swz64(d, seg);
            cp_async16(sbase + R_BH + so, XH + (size_t)d * Tv + seg * 8);
            cp_async16(sbase + R_BL + so, XL + (size_t)d * Tv + seg * 8);
        }
        CP_COMMIT();
#pragma unroll
        for (int l = 0; l < 4; l++) {
            int q = tid + l * 128, row = q >> 3;
            float4 v = *(const float4*)&A[(size_t)row * Tv + ac4 * 4];
            uint2 hi, lo;
            split4(v, hi, lo);
            uint32_t so = swz64(row, ac4 >> 1) + (ac4 & 1) * 8;
            *(uint2*)(smem + R_AH + so) = hi;
            *(uint2*)(smem + R_AL + so) = lo;
        }
        CP_WAIT0();
        __syncthreads();
    }

    for (int c = 0; c < NCHUNK; c++) {
        const int s = c & 1;
        const uint32_t bb = sbase + s * R_STAGE;
        const bool more = (c + 1 < NCHUNK);
        float4 pa[4];
        if (more) {
            const int k1 = (c + 1) * 32;
            const uint32_t nbuf = sbase + (s ^ 1) * R_STAGE;
#pragma unroll
            for (int l = 0; l < 8; l++) {
                int q = tid + l * 128, d = q >> 2, seg = q & 3;
                uint32_t so = swz64(d, seg);
                cp_async16(nbuf + R_BH + so, XH + (size_t)d * Tv + k1 + seg * 8);
                cp_async16(nbuf + R_BL + so, XL + (size_t)d * Tv + k1 + seg * 8);
            }
            CP_COMMIT();
#pragma unroll
            for (int l = 0; l < 4; l++) {
                int q = tid + l * 128, row = q >> 3;
                pa[l] = *(const float4*)&A[(size_t)row * Tv + k1 + ac4 * 4];
            }
        }
#pragma unroll
        for (int ks = 0; ks < 2; ks++) {
            uint32_t ah[4][4];
#pragma unroll
            for (int i = 0; i < 4; i++) {
                int row = 16 * i + a_rrel;
                uint32_t ao = (uint32_t)(row * 64 +
                    (((ks * 2 + a_matk) ^ a_msk) << 4));
                LDM4(ah[i][0], ah[i][1], ah[i][2], ah[i][3], bb + R_AH + ao);
            }
            uint32_t bh[8][2];
#pragma unroll
            for (int jj = 0; jj < 4; jj++) {
                int row = n0w + 16 * jj + b_rrel;
                uint32_t bo = (uint32_t)(row * 64 +
                    (((ks * 2 + b_matk) ^ b_msk) << 4));
                LDM4(bh[2 * jj][0], bh[2 * jj][1], bh[2 * jj + 1][0],
                     bh[2 * jj + 1][1], bb + R_BH + bo);
            }
#pragma unroll
            for (int i = 0; i < 4; i++)
#pragma unroll
                for (int j = 0; j < 8; j++)
                    mma_bf16(acc[i][j], ah[i], bh[j]);
            uint32_t bl[8][2];
#pragma unroll
            for (int jj = 0; jj < 4; jj++) {
                int row = n0w + 16 * jj + b_rrel;
                uint32_t bo = (uint32_t)(row * 64 +
                    (((ks * 2 + b_matk) ^ b_msk) << 4));
                LDM4(bl[2 * jj][0], bl[2 * jj][1], bl[2 * jj + 1][0],
                     bl[2 * jj + 1][1], bb + R_BL + bo);
            }
#pragma unroll
            for (int i = 0; i < 4; i++)
#pragma unroll
                for (int j = 0; j < 8; j++)
                    mma_bf16(acc[i][j], ah[i], bl[j]);
            uint32_t al[4][4];
#pragma unroll
            for (int i = 0; i < 4; i++) {
                int row = 16 * i + a_rrel;
                uint32_t ao = (uint32_t)(row * 64 +
                    (((ks * 2 + a_matk) ^ a_msk) << 4));
                LDM4(al[i][0], al[i][1], al[i][2], al[i][3], bb + R_AL + ao);
            }
#pragma unroll
            for (int i = 0; i < 4; i++)
#pragma unroll
                for (int j = 0; j < 8; j++)
                    mma_bf16(acc[i][j], al[i], bh[j]);
        }
        if (more) {
            char* nb = smem + (s ^ 1) * R_STAGE;
#pragma unroll
            for (int l = 0; l < 4; l++) {
                int q = tid + l * 128, row = q >> 3;
                uint2 hi, lo;
                split4(pa[l], hi, lo);
                uint32_t so = swz64(row, ac4 >> 1) + (ac4 & 1) * 8;
                *(uint2*)(nb + R_AH + so) = hi;
                *(uint2*)(nb + R_AL + so) = lo;
            }
        }
        CP_WAIT0();
        __syncthreads();
    }

    const int g = lane >> 2, t2 = (lane & 3) * 2;
#pragma unroll
    for (int i = 0; i < 4; i++)
#pragma unroll
        for (int j = 0; j < 8; j++) {
            int rr = 16 * i + g, cc = n0w + 8 * j + t2;
            *(float2*)&C[(size_t)rr * Dv + cc] =
                make_float2(acc[i][j][0], acc[i][j][1]);
            *(float2*)&C[(size_t)(rr + 8) * Dv + cc] =
                make_float2(acc[i][j][2], acc[i][j][3]);
        }
}

// ---------------- kernel 2: MLP + fused logits/KL/argmax, 32x256 tile --------
#define M_AH 0
#define M_AL 2048
#define M_BH 4096
#define M_BL 20480
#define M_STAGE 36864
#define M_SMEM (2 * M_STAGE)
#define M_NCHUNK 24

__global__ __launch_bounds__(128, 2)
void gemm_mlp_mma(const float* __restrict__ b1, const float* __restrict__ w2,
                  const float* __restrict__ b2, const float* __restrict__ label,
                  const int* __restrict__ mask) {
    extern __shared__ char smem[];
    const uint32_t sbase = smem_u32(smem);
    const int tid = threadIdx.x, wid = tid >> 5, lane = tid & 31;
    const int row0 = blockIdx.x * 32;

    const int n0w = wid * 64;
    const int mat = lane >> 3, r8 = lane & 7;
    const int a_rrel = (mat & 1) * 8 + r8;
    const int a_msk  = (a_rrel >> 1) & 3;
    const int a_matk = mat >> 1;
    const int b_rrel = (mat >> 1) * 8 + r8;
    const int b_msk  = (b_rrel >> 1) & 3;
    const int b_matk = mat & 1;
    const int ac4 = tid & 7;

    float acc[2][8][4];
#pragma unroll
    for (int i = 0; i < 2; i++)
#pragma unroll
        for (int j = 0; j < 8; j++)
#pragma unroll
            for (int q = 0; q < 4; q++) acc[i][j][q] = 0.f;

    {
#pragma unroll
        for (int l = 0; l < 8; l++) {
            int q = tid + l * 128, d = q >> 2, seg = q & 3;
            uint32_t so = swz64(d, seg);
            cp_async16(sbase + M_BH + so, g_w1h + (size_t)d * (3 * Dv) + seg * 8);
            cp_async16(sbase + M_BL + so, g_w1l + (size_t)d * (3 * Dv) + seg * 8);
        }
        CP_COMMIT();
#pragma unroll
        for (int l = 0; l < 2; l++) {
            int q = tid + l * 128, row = q >> 3;
            float4 v = *(const float4*)&g_hr[(size_t)(row0 + row) * Dv + ac4 * 4];
            uint2 hi, lo;
            split4(v, hi, lo);
            uint32_t so = swz64(row, ac4 >> 1) + (ac4 & 1) * 8;
            *(uint2*)(smem + M_AH + so) = hi;
            *(uint2*)(smem + M_AL + so) = lo;
        }
        CP_WAIT0();
        __syncthreads();
    }

    for (int c = 0; c < M_NCHUNK; c++) {
        const int s = c & 1;
        const uint32_t bb = sbase + s * M_STAGE;
        const bool more = (c + 1 < M_NCHUNK);
        float4 pa[2], pt[2];
        int nregion = 0;
        if (more) {
            const int c1 = c + 1;
            nregion = c1 >> 3;
            const int kk = (c1 & 7) * 32;
            const int k1 = c1 * 32;
            const uint32_t nbuf = sbase + (s ^ 1) * M_STAGE;
#pragma unroll
            for (int l = 0; l < 8; l++) {
                int q = tid + l * 128, d = q >> 2, seg = q & 3;
                uint32_t so = swz64(d, seg);
                cp_async16(nbuf + M_BH + so,
                           g_w1h + (size_t)d * (3 * Dv) + k1 + seg * 8);
                cp_async16(nbuf + M_BL + so,
                           g_w1l + (size_t)d * (3 * Dv) + k1 + seg * 8);
            }
            CP_COMMIT();
#pragma unroll
            for (int l = 0; l < 2; l++) {
                int q = tid + l * 128, row = q >> 3;
                size_t off = (size_t)(row0 + row) * Dv + kk + ac4 * 4;
                if (nregion == 0) pa[l] = *(const float4*)&g_hr[off];
                else if (nregion == 1) pa[l] = *(const float4*)&g_tr[off];
                else {
                    pa[l] = *(const float4*)&g_hr[off];
                    pt[l] = *(const float4*)&g_tr[off];
                }
            }
        }
#pragma unroll
        for (int ks = 0; ks < 2; ks++) {
            uint32_t ah[2][4];
#pragma unroll
            for (int i = 0; i < 2; i++) {
                int row = 16 * i + a_rrel;
                uint32_t ao = (uint32_t)(row * 64 +
                    (((ks * 2 + a_matk) ^ a_msk) << 4));
                LDM4(ah[i][0], ah[i][1], ah[i][2], ah[i][3], bb + M_AH + ao);
            }
            uint32_t bh[8][2];
#pragma unroll
            for (int jj = 0; jj < 4; jj++) {
                int row = n0w + 16 * jj + b_rrel;
                uint32_t bo = (uint32_t)(row * 64 +
                    (((ks * 2 + b_matk) ^ b_msk) << 4));
                LDM4(bh[2 * jj][0], bh[2 * jj][1], bh[2 * jj + 1][0],
                     bh[2 * jj + 1][1], bb + M_BH + bo);
            }
#pragma unroll
            for (int i = 0; i < 2; i++)
#pragma unroll
                for (int j = 0; j < 8; j++)
                    mma_bf16(acc[i][j], ah[i], bh[j]);
            uint32_t bl[8][2];
#pragma unroll
            for (int jj = 0; jj < 4; jj++) {
                int row = n0w + 16 * jj + b_rrel;
                uint32_t bo = (uint32_t)(row * 64 +
                    (((ks * 2 + b_matk) ^ b_msk) << 4));
                LDM4(bl[2 * jj][0], bl[2 * jj][1], bl[2 * jj + 1][0],
                     bl[2 * jj + 1][1], bb + M_BL + bo);
            }
#pragma unroll
            for (int i = 0; i < 2; i++)
#pragma unroll
                for (int j = 0; j < 8; j++)
                    mma_bf16(acc[i][j], ah[i], bl[j]);
            uint32_t al[2][4];
#pragma unroll
            for (int i = 0; i < 2; i++) {
                int row = 16 * i + a_rrel;
                uint32_t ao = (uint32_t)(row * 64 +
                    (((ks * 2 + a_matk) ^ a_msk) << 4));
                LDM4(al[i][0], al[i][1], al[i][2], al[i][3], bb + M_AL + ao);
            }
#pragma unroll
            for (int i = 0; i < 2; i++)
#pragma unroll
                for (int j = 0; j < 8; j++)
                    mma_bf16(acc[i][j], al[i], bh[j]);
        }
        if (more) {
            char* nb = smem + (s ^ 1) * M_STAGE;
#pragma unroll
            for (int l = 0; l < 2; l++) {
                int q = tid + l * 128, row = q >> 3;
                float4 v = pa[l];
                if (nregion == 2) {
                    v.x *= pt[l].x; v.y *= pt[l].y; v.z *= pt[l].z; v.w *= pt[l].w;
                }
                uint2 hi, lo;
                split4(v, hi, lo);
                uint32_t so = swz64(row, ac4 >> 1) + (ac4 & 1) * 8;
                *(uint2*)(nb + M_AH + so) = hi;
                *(uint2*)(nb + M_AL + so) = lo;
            }
        }
        CP_WAIT0();
        __syncthreads();
    }

    // ---- fused epilogue: relu(acc+b1) @ w2 partials, reduce, KL, argmax -----
    const int g = lane >> 2, t2 = (lane & 3) * 2;
    float s0[4] = {0.f, 0.f, 0.f, 0.f}, s1[4] = {0.f, 0.f, 0.f, 0.f};
#pragma unroll
    for (int j = 0; j < 8; j++)
#pragma unroll
        for (int e = 0; e < 2; e++) {
            int col = n0w + 8 * j + t2 + e;
            float bb1 = b1[col];
            float w20 = w2[col * 2], w21 = w2[col * 2 + 1];
#pragma unroll
            for (int i = 0; i < 2; i++) {
                float h0 = fmaxf(acc[i][j][e] + bb1, 0.f);       // row 16i+g
                float h1 = fmaxf(acc[i][j][e + 2] + bb1, 0.f);   // row 16i+8+g
                s0[i * 2 + 0] = fmaf(h0, w20, s0[i * 2 + 0]);
                s1[i * 2 + 0] = fmaf(h0, w21, s1[i * 2 + 0]);
                s0[i * 2 + 1] = fmaf(h1, w20, s0[i * 2 + 1]);
                s1[i * 2 + 1] = fmaf(h1, w21, s1[i * 2 + 1]);
            }
        }
#pragma unroll
    for (int sl = 0; sl < 4; sl++) {
        s0[sl] += __shfl_xor_sync(0xffffffffu, s0[sl], 1);
        s0[sl] += __shfl_xor_sync(0xffffffffu, s0[sl], 2);
        s1[sl] += __shfl_xor_sync(0xffffffffu, s1[sl], 1);
        s1[sl] += __shfl_xor_sync(0xffffffffu, s1[sl], 2);
    }
    float* sred = (float*)smem;   // [4 warps][32 rows][2]
    if ((lane & 3) == 0) {
#pragma unroll
        for (int sl = 0; sl < 4; sl++) {
            int row = (sl >> 1) * 16 + (sl & 1) * 8 + g;
            sred[(wid * 32 + row) * 2 + 0] = s0[sl];
            sred[(wid * 32 + row) * 2 + 1] = s1[sl];
        }
    }
    __syncthreads();
    if (tid < 32) {
        int r = tid;
        float l0 = b2[0], l1 = b2[1];
#pragma unroll
        for (int w = 0; w < 4; w++) {
            l0 += sred[(w * 32 + r) * 2 + 0];
            l1 += sred[(w * 32 + r) * 2 + 1];
        }
        int gw = row0 + r;
        float mx = fmaxf(l0, l1);
        float lse = mx + logf(expf(l0 - mx) + expf(l1 - mx));
        float a0 = label[gw * 2 + 0];
        float a1 = label[gw * 2 + 1];
        float pw = (a0 > 0.f ? a0 * logf(fmaxf(a0, 1e-38f)) : 0.f) - a0 * (l0 - lse)
                 + (a1 > 0.f ? a1 * logf(fmaxf(a1, 1e-38f)) : 0.f) - a1 * (l1 - lse);
        g_pw[gw] = mask[gw] ? pw : 0.f;
        // fused per-mention argmax over the 16-lane group (first-max semantics)
        float v = l1;
        int idx = r & 15;
#pragma unroll
        for (int o = 8; o; o >>= 1) {
            float ov = __shfl_down_sync(0xffffffffu, v, o, 16);
            int oi = __shfl_down_sync(0xffffffffu, idx, o, 16);
            if (ov > v || (ov == v && oi < idx)) { v = ov; idx = oi; }
        }
        if ((r & 15) == 0) {
            int mention = gw >> 4;     // global index into [Bv*Mv)
            g_seli[mention] = idx;
            g_selv[mention] = v;
        }
    }
}

// ---------------- kernel 3: select+transpose, plus loss slice (z==Bv) --------
// grid (Mv/32, Dv/32, Bv+1); z<Bv: gather/transpose; z==Bv,(x,y)==(0,0): loss.
__global__ void select_transpose(const int* __restrict__ mask,
                                 float* __restrict__ out_loss) {
    __shared__ float tile[32][33];
    __shared__ int sidx[32];
    __shared__ float sval[32];
    const int tx = threadIdx.x, ty = threadIdx.y;

    if (blockIdx.z == Bv) {
        if (blockIdx.x != 0 || blockIdx.y != 0) return;
        // ---- deterministic loss reduction with 256 threads ----
        __shared__ float sh[256];
        __shared__ int shc[256];
        const int tid = ty * 32 + tx;
        float s = 0.f;
        int c = 0;
        for (int i = tid; i < Bv * Pv; i += 256) {
            s += g_pw[i];
            c += mask[i] ? 1 : 0;
        }
        sh[tid] = s;
        shc[tid] = c;
        __syncthreads();
        for (int o = 128; o; o >>= 1) {
            if (tid < o) { sh[tid] += sh[tid + o]; shc[tid] += shc[tid + o]; }
            __syncthreads();
        }
        if (tid == 0) *out_loss = sh[0] / ((float)shc[0] * 2.0f);
        return;
    }

    const int b = blockIdx.z, m0 = blockIdx.x * 32, d0 = blockIdx.y * 32;
    if (ty == 0) {
        sidx[tx] = g_seli[b * Mv + m0 + tx];
        sval[tx] = g_selv[b * Mv + m0 + tx];
    }
    __syncthreads();
#pragma unroll
    for (int i = 0; i < 4; i++) {
        int m = ty + 8 * i;
        size_t row = (size_t)b * Pv + (size_t)(m0 + m) * Lv + sidx[m];
        tile[m][tx] = g_tr[row * Dv + d0 + tx] * sval[m];
    }
    __syncthreads();
#pragma unroll
    for (int i = 0; i < 4; i++) {
        int d = d0 + ty + 8 * i, m = m0 + tx;
        float v = tile[tx][ty + 8 * i];
        __nv_bfloat16 h = __float2bfloat16(v);
        size_t off = ((size_t)b * Dv + d) * Mv + m;
        g_rmh[off] = h;
        g_rml[off] = __float2bfloat16(v - __bfloat162float(h));
    }
}

// ---------------- kernel 4: merge via bf16x3 mma: out = x + cmp^T @ repm -----
#define G_NCHUNK 4

__global__ __launch_bounds__(128, 2)
void merge_mma(const float* __restrict__ x, const float* __restrict__ cmp,
               float* __restrict__ out) {
    extern __shared__ char smem[];
    const uint32_t sbase = smem_u32(smem);
    const int tid = threadIdx.x, wid = tid >> 5, lane = tid & 31;
    const int b = blockIdx.y, t0 = blockIdx.x * 64;
    const float* CM = cmp + (size_t)b * Mv * Tv;
    const __nv_bfloat16* RH = g_rmh + (size_t)b * Dv * Mv;
    const __nv_bfloat16* RL = g_rml + (size_t)b * Dv * Mv;

    const int n0w = wid * 64;
    const int mat = lane >> 3, r8 = lane & 7;
    const int a_rrel = (mat & 1) * 8 + r8;
    const int a_msk  = (a_rrel >> 1) & 3;
    const int a_matk = mat >> 1;
    const int b_rrel = (mat >> 1) * 8 + r8;
    const int b_msk  = (b_rrel >> 1) & 3;
    const int b_matk = mat & 1;

    const int am = tid >> 2, atoff = (tid & 3) * 16;

    float acc[4][8][4];
#pragma unroll
    for (int i = 0; i < 4; i++)
#pragma unroll
        for (int j = 0; j < 8; j++)
#pragma unroll
            for (int q = 0; q < 4; q++) acc[i][j][q] = 0.f;

    {
#pragma unroll
        for (int l = 0; l < 8; l++) {
            int q = tid + l * 128, d = q >> 2, seg = q & 3;
            uint32_t so = swz64(d, seg);
            cp_async16(sbase + R_BH + so, RH + (size_t)d * Mv + seg * 8);
            cp_async16(sbase + R_BL + so, RL + (size_t)d * Mv + seg * 8);
        }
        CP_COMMIT();
#pragma unroll
        for (int l = 0; l < 4; l++) {
            float4 v = *(const float4*)&CM[(size_t)am * Tv + t0 + atoff + l * 4];
            float f[4] = {v.x, v.y, v.z, v.w};
#pragma unroll
            for (int fi = 0; fi < 4; fi++) {
                int t = atoff + l * 4 + fi;
                __nv_bfloat16 h = __float2bfloat16(f[fi]);
                uint32_t so = (uint32_t)(t * 64 +
                    ((((am >> 3) ^ ((t >> 1) & 3)) << 4)) + (am & 7) * 2);
                *(__nv_bfloat16*)(smem + R_AH + so) = h;
                *(__nv_bfloat16*)(smem + R_AL + so) =
                    __float2bfloat16(f[fi] - __bfloat162float(h));
            }
        }
        CP_WAIT0();
        __syncthreads();
    }

    for (int c = 0; c < G_NCHUNK; c++) {
        const int s = c & 1;
        const uint32_t bb = sbase + s * R_STAGE;
        const bool more = (c + 1 < G_NCHUNK);
        float4 pa[4];
        if (more) {
            const int m1 = (c + 1) * 32;
            const uint32_t nbuf = sbase + (s ^ 1) * R_STAGE;
#pragma unroll
            for (int l = 0; l < 8; l++) {
                int q = tid + l * 128, d = q >> 2, seg = q & 3;
                uint32_t so = swz64(d, seg);
                cp_async16(nbuf + R_BH + so, RH + (size_t)d * Mv + m1 + seg * 8);
                cp_async16(nbuf + R_BL + so, RL + (size_t)d * Mv + m1 + seg * 8);
            }
            CP_COMMIT();
#pragma unroll
            for (int l = 0; l < 4; l++)
                pa[l] = *(const float4*)&CM[(size_t)(m1 + am) * Tv + t0 + atoff + l * 4];
        }
#pragma unroll
        for (int ks = 0; ks < 2; ks++) {
            uint32_t ah[4][4];
#pragma unroll
            for (int i = 0; i < 4; i++) {
                int row = 16 * i + a_rrel;
                uint32_t ao = (uint32_t)(row * 64 +
                    (((ks * 2 + a_matk) ^ a_msk) << 4));
                LDM4(ah[i][0], ah[i][1], ah[i][2], ah[i][3], bb + R_AH + ao);
            }
            uint32_t bh[8][2];
#pragma unroll
            for (int jj = 0; jj < 4; jj++) {
                int row = n0w + 16 * jj + b_rrel;
                uint32_t bo = (uint32_t)(row * 64 +
                    (((ks * 2 + b_matk) ^ b_msk) << 4));
                LDM4(bh[2 * jj][0], bh[2 * jj][1], bh[2 * jj + 1][0],
                     bh[2 * jj + 1][1], bb + R_BH + bo);
            }
#pragma unroll
            for (int i = 0; i < 4; i++)
#pragma unroll
                for (int j = 0; j < 8; j++)
                    mma_bf16(acc[i][j], ah[i], bh[j]);
            uint32_t bl[8][2];
#pragma unroll
            for (int jj = 0; jj < 4; jj++) {
                int row = n0w + 16 * jj + b_rrel;
                uint32_t bo = (uint32_t)(row * 64 +
                    (((ks * 2 + b_matk) ^ b_msk) << 4));
                LDM4(bl[2 * jj][0], bl[2 * jj][1], bl[2 * jj + 1][0],
                     bl[2 * jj + 1][1], bb + R_BL + bo);
            }
#pragma unroll
            for (int i = 0; i < 4; i++)
#pragma unroll
                for (int j = 0; j < 8; j++)
                    mma_bf16(acc[i][j], ah[i], bl[j]);
            uint32_t al[4][4];
#pragma unroll
            for (int i = 0; i < 4; i++) {
                int row = 16 * i + a_rrel;
                uint32_t ao = (uint32_t)(row * 64 +
                    (((ks * 2 + a_matk) ^ a_msk) << 4));
                LDM4(al[i][0], al[i][1], al[i][2], al[i][3], bb + R_AL + ao);
            }
#pragma unroll
            for (int i = 0; i < 4; i++)
#pragma unroll
                for (int j = 0; j < 8; j++)
                    mma_bf16(acc[i][j], al[i], bh[j]);
        }
        if (more) {
            char* nb = smem + (s ^ 1) * R_STAGE;
#pragma unroll
            for (int l = 0; l < 4; l++) {
                float f[4] = {pa[l].x, pa[l].y, pa[l].z, pa[l].w};
#pragma unroll
                for (int fi = 0; fi < 4; fi++) {
                    int t = atoff + l * 4 + fi;
                    __nv_bfloat16 h = __float2bfloat16(f[fi]);
                    uint32_t so = (uint32_t)(t * 64 +
                        ((((am >> 3) ^ ((t >> 1) & 3)) << 4)) + (am & 7) * 2);
                    *(__nv_bfloat16*)(nb + R_AH + so) = h;
                    *(__nv_bfloat16*)(nb + R_AL + so) =
                        __float2bfloat16(f[fi] - __bfloat162float(h));
                }
            }
        }
        CP_WAIT0();
        __syncthreads();
    }

    const int g = lane >> 2, t2 = (lane & 3) * 2;
#pragma unroll
    for (int i = 0; i < 4; i++)
#pragma unroll
        for (int j = 0; j < 8; j++) {
            int rr = t0 + 16 * i + g, cc = n0w + 8 * j + t2;
            size_t base = ((size_t)b * Tv + rr) * Dv + cc;
            float2 x0 = *(const float2*)&x[base];
            float2 x1 = *(const float2*)&x[base + (size_t)8 * Dv];
            *(float2*)&out[base] =
                make_float2(x0.x + acc[i][j][0], x0.y + acc[i][j][1]);
            *(float2*)&out[base + (size_t)8 * Dv] =
                make_float2(x1.x + acc[i][j][2], x1.y + acc[i][j][3]);
        }
}

// ---------------- launch -----------------------------------------------------
extern "C" void kernel_launch(void* const* d_in, const int* in_sizes, int n_in,
                              void* d_out, int out_size) {
    const float* head = (const float*)d_in[0];
    const float* tail = (const float*)d_in[1];
    /* d_in[2] = lens (unused: uniform L) */
    const float* x    = (const float*)d_in[3];
    const float* cmp  = (const float*)d_in[4];
    const float* lab  = (const float*)d_in[5];
    const int*   mask = (const int*)d_in[6];
    const float* w1 = (const float*)d_in[7];
    const float* b1 = (const float*)d_in[8];
    const float* w2 = (const float*)d_in[9];
    const float* b2 = (const float*)d_in[10];
    float* out = (float*)d_out;

    cudaFuncSetAttribute(gemm_rep_mma,
                         cudaFuncAttributeMaxDynamicSharedMemorySize, R_SMEM);
    cudaFuncSetAttribute(gemm_mlp_mma,
                         cudaFuncAttributeMaxDynamicSharedMemorySize, M_SMEM);
    cudaFuncSetAttribute(merge_mma,
                         cudaFuncAttributeMaxDynamicSharedMemorySize, R_SMEM);

    prep_all<<<dim3(Tv / 32, Dv / 32, Bv + 1), dim3(32, 8)>>>(x, w1); // #1
    gemm_rep_mma<<<dim3(Pv / 64, Bv * 2), 128, R_SMEM>>>(head, tail); // #2
    gemm_mlp_mma<<<(Bv * Pv) / 32, 128, M_SMEM>>>(b1, w2, b2, lab, mask); // #3
    select_transpose<<<dim3(Mv / 32, Dv / 32, Bv + 1), dim3(32, 8)>>>(
        mask, out + (out_size - 1));                                  // #4 (+loss)
    merge_mma<<<dim3(Tv / 64, Bv), 128, R_SMEM>>>(x, cmp, out);       // #5
}